// round 1
// baseline (speedup 1.0000x reference)
#include <cuda_runtime.h>

// Problem constants
#define Bc   4
#define Sc   2048
#define Dc   768
#define Hc   12
#define HDc  64
#define Mrows (Bc * Sc)   // 8192

// Scratch for projected q, k, v in [B, S, D] layout (75.5 MB total, device globals)
__device__ float g_q[(size_t)Mrows * Dc];
__device__ float g_k[(size_t)Mrows * Dc];
__device__ float g_v[(size_t)Mrows * Dc];

// ---------------------------------------------------------------------------
// Linear: Y = X @ W^T + b        X:[8192,768]  W:[768,768]  Y:[8192,768]
// 128x128 tile, BK=16, 256 threads, 8x8 micro-tile per thread.
// Smem stored k-major (transposed on load) so the inner loop reads float4s.
// ---------------------------------------------------------------------------
__global__ __launch_bounds__(256) void linear_kernel(
    const float* __restrict__ X,
    const float* __restrict__ W,
    const float* __restrict__ bias,
    int which)
{
    float* Y = (which == 0) ? g_q : (which == 1) ? g_k : g_v;

    __shared__ __align__(16) float As[16 * 132];
    __shared__ __align__(16) float Bs[16 * 132];

    const int tid = threadIdx.x;
    const int ty = tid >> 4;        // 0..15
    const int tx = tid & 15;        // 0..15
    const int bm = blockIdx.y * 128;
    const int bn = blockIdx.x * 128;

    float acc[8][8];
#pragma unroll
    for (int i = 0; i < 8; i++)
#pragma unroll
        for (int j = 0; j < 8; j++) acc[i][j] = 0.0f;

    for (int k0 = 0; k0 < Dc; k0 += 16) {
        // Load 128x16 tiles of X and W, transposed into k-major smem.
#pragma unroll
        for (int i = 0; i < 8; i++) {
            int idx = tid + i * 256;        // 0..2047
            int r = idx >> 4;               // 0..127
            int c = idx & 15;               // 0..15
            As[c * 132 + r] = X[(bm + r) * Dc + k0 + c];
            Bs[c * 132 + r] = W[(bn + r) * Dc + k0 + c];
        }
        __syncthreads();

#pragma unroll
        for (int k = 0; k < 16; k++) {
            float4 a0 = *(const float4*)&As[k * 132 + ty * 8];
            float4 a1 = *(const float4*)&As[k * 132 + ty * 8 + 4];
            float4 b0 = *(const float4*)&Bs[k * 132 + tx * 8];
            float4 b1 = *(const float4*)&Bs[k * 132 + tx * 8 + 4];
            float a[8] = {a0.x, a0.y, a0.z, a0.w, a1.x, a1.y, a1.z, a1.w};
            float bb[8] = {b0.x, b0.y, b0.z, b0.w, b1.x, b1.y, b1.z, b1.w};
#pragma unroll
            for (int i = 0; i < 8; i++)
#pragma unroll
                for (int j = 0; j < 8; j++)
                    acc[i][j] += a[i] * bb[j];
        }
        __syncthreads();
    }

#pragma unroll
    for (int i = 0; i < 8; i++) {
        int row = bm + ty * 8 + i;
#pragma unroll
        for (int j = 0; j < 8; j++) {
            int col = bn + tx * 8 + j;
            Y[row * Dc + col] = acc[i][j] + bias[col];
        }
    }
}

// ---------------------------------------------------------------------------
// Flash attention with dual-stream scores:
//   S = (Q K^T + LQ LK^T) * scale + mask ; softmax ; O = P V
// One block per (b, h, 64-query tile). 64-key tiles. 256 threads,
// 4x4 score micro-tiles (ty = query group, tx = key/dim group).
// ---------------------------------------------------------------------------
#define PAD 65
#define SMEM_ATTN ((6 * 64 * PAD + 64) * (int)sizeof(float))   // 100096 B

__global__ __launch_bounds__(256) void attn_kernel(
    const float* __restrict__ lq_in,
    const float* __restrict__ lk_in,
    const float* __restrict__ mask,
    float* __restrict__ out)
{
    extern __shared__ float smbuf[];
    float* Qs  = smbuf;
    float* LQs = Qs  + 64 * PAD;
    float* Ks  = LQs + 64 * PAD;
    float* LKs = Ks  + 64 * PAD;
    float* Vs  = LKs + 64 * PAD;
    float* Ps  = Vs  + 64 * PAD;
    float* msh = Ps  + 64 * PAD;   // [64] mask slice

    const int tid = threadIdx.x;
    const int ty = tid >> 4;           // 0..15  -> query rows ty*4..ty*4+3
    const int tx = tid & 15;           // 0..15  -> key cols / dims tx*4..tx*4+3
    const int rowbase = ty * 4;
    const int colbase = tx * 4;

    const int b  = blockIdx.z;
    const int h  = blockIdx.y;
    const int q0 = blockIdx.x * 64;
    const int hoff = h * HDc;
    const float scale = 0.125f;        // 1/sqrt(64)

    // Load Q and LQ tiles (once)
#pragma unroll
    for (int t = 0; t < 4; t++) {
        int idx = tid + t * 256;       // 0..1023
        int r = idx >> 4;              // 0..63
        int c4 = (idx & 15) << 2;      // 0,4,...,60
        int g = (b * Sc + q0 + r) * Dc + hoff + c4;
        float4 qv = *(const float4*)&g_q[g];
        float4 lv = *(const float4*)&lq_in[g];
        Qs[r * PAD + c4 + 0] = qv.x;  Qs[r * PAD + c4 + 1] = qv.y;
        Qs[r * PAD + c4 + 2] = qv.z;  Qs[r * PAD + c4 + 3] = qv.w;
        LQs[r * PAD + c4 + 0] = lv.x; LQs[r * PAD + c4 + 1] = lv.y;
        LQs[r * PAD + c4 + 2] = lv.z; LQs[r * PAD + c4 + 3] = lv.w;
    }

    float m_[4], l_[4], o_[4][4];
#pragma unroll
    for (int i = 0; i < 4; i++) {
        m_[i] = -1e30f;
        l_[i] = 0.0f;
#pragma unroll
        for (int j = 0; j < 4; j++) o_[i][j] = 0.0f;
    }

    for (int kt = 0; kt < Sc / 64; kt++) {
        __syncthreads();   // previous iteration done with Ks/LKs/Vs/msh (and Q load on iter 0)

        // Load K, LK, V tiles + mask slice
#pragma unroll
        for (int t = 0; t < 4; t++) {
            int idx = tid + t * 256;
            int r = idx >> 4;
            int c4 = (idx & 15) << 2;
            int g = (b * Sc + kt * 64 + r) * Dc + hoff + c4;
            float4 kv = *(const float4*)&g_k[g];
            float4 lv = *(const float4*)&lk_in[g];
            float4 vv = *(const float4*)&g_v[g];
            Ks[r * PAD + c4 + 0] = kv.x;  Ks[r * PAD + c4 + 1] = kv.y;
            Ks[r * PAD + c4 + 2] = kv.z;  Ks[r * PAD + c4 + 3] = kv.w;
            LKs[r * PAD + c4 + 0] = lv.x; LKs[r * PAD + c4 + 1] = lv.y;
            LKs[r * PAD + c4 + 2] = lv.z; LKs[r * PAD + c4 + 3] = lv.w;
            Vs[r * PAD + c4 + 0] = vv.x;  Vs[r * PAD + c4 + 1] = vv.y;
            Vs[r * PAD + c4 + 2] = vv.z;  Vs[r * PAD + c4 + 3] = vv.w;
        }
        if (tid < 64) msh[tid] = mask[b * Sc + kt * 64 + tid];
        __syncthreads();

        // Scores: (Q.K + LQ.LK)
        float sc[4][4];
#pragma unroll
        for (int i = 0; i < 4; i++)
#pragma unroll
            for (int j = 0; j < 4; j++) sc[i][j] = 0.0f;

#pragma unroll 8
        for (int k = 0; k < 64; k++) {
            float a[4], la[4], bb[4], lb[4];
#pragma unroll
            for (int i = 0; i < 4; i++) {
                a[i]  = Qs[(rowbase + i) * PAD + k];
                la[i] = LQs[(rowbase + i) * PAD + k];
            }
#pragma unroll
            for (int j = 0; j < 4; j++) {
                bb[j] = Ks[(colbase + j) * PAD + k];
                lb[j] = LKs[(colbase + j) * PAD + k];
            }
#pragma unroll
            for (int i = 0; i < 4; i++)
#pragma unroll
                for (int j = 0; j < 4; j++)
                    sc[i][j] += a[i] * bb[j] + la[i] * lb[j];
        }

        float mj[4];
#pragma unroll
        for (int j = 0; j < 4; j++) mj[j] = msh[colbase + j];

        // Online softmax (row groups of 16 threads; reductions via shfl within 16-lane groups)
#pragma unroll
        for (int i = 0; i < 4; i++) {
#pragma unroll
            for (int j = 0; j < 4; j++) sc[i][j] = sc[i][j] * scale + mj[j];

            float mx = fmaxf(fmaxf(sc[i][0], sc[i][1]), fmaxf(sc[i][2], sc[i][3]));
#pragma unroll
            for (int o = 1; o < 16; o <<= 1)
                mx = fmaxf(mx, __shfl_xor_sync(0xffffffffu, mx, o));

            float mnew  = fmaxf(m_[i], mx);
            float alpha = __expf(m_[i] - mnew);

            float p[4], psum = 0.0f;
#pragma unroll
            for (int j = 0; j < 4; j++) { p[j] = __expf(sc[i][j] - mnew); psum += p[j]; }
#pragma unroll
            for (int o = 1; o < 16; o <<= 1)
                psum += __shfl_xor_sync(0xffffffffu, psum, o);

            l_[i] = l_[i] * alpha + psum;
            m_[i] = mnew;
#pragma unroll
            for (int j = 0; j < 4; j++) {
                o_[i][j] *= alpha;
                Ps[(rowbase + i) * PAD + colbase + j] = p[j];
            }
        }
        // Ps rows for this ty group are written and read only by threads of the same
        // 16-thread group (same warp) -> warp sync suffices.
        __syncwarp();

        // O += P @ V
#pragma unroll 8
        for (int k = 0; k < 64; k++) {
            float pa[4], vb[4];
#pragma unroll
            for (int i = 0; i < 4; i++) pa[i] = Ps[(rowbase + i) * PAD + k];
#pragma unroll
            for (int j = 0; j < 4; j++) vb[j] = Vs[k * PAD + colbase + j];
#pragma unroll
            for (int i = 0; i < 4; i++)
#pragma unroll
                for (int j = 0; j < 4; j++)
                    o_[i][j] += pa[i] * vb[j];
        }
    }

    // Normalize and store (output layout [B, S, H*HD])
#pragma unroll
    for (int i = 0; i < 4; i++) {
        float inv = 1.0f / l_[i];
        float4 ov = make_float4(o_[i][0] * inv, o_[i][1] * inv,
                                o_[i][2] * inv, o_[i][3] * inv);
        *(float4*)&out[(b * Sc + q0 + rowbase + i) * Dc + hoff + colbase] = ov;
    }
}

// ---------------------------------------------------------------------------
// Launch
// ---------------------------------------------------------------------------
extern "C" void kernel_launch(void* const* d_in, const int* in_sizes, int n_in,
                              void* d_out, int out_size)
{
    const float* hs   = (const float*)d_in[0];
    const float* lq   = (const float*)d_in[1];
    const float* lk   = (const float*)d_in[2];
    const float* mask = (const float*)d_in[3];
    const float* Wq   = (const float*)d_in[4];
    const float* bq   = (const float*)d_in[5];
    const float* Wk   = (const float*)d_in[6];
    const float* bk   = (const float*)d_in[7];
    const float* Wv   = (const float*)d_in[8];
    const float* bv   = (const float*)d_in[9];
    float* out = (float*)d_out;

    dim3 gl(Dc / 128, Mrows / 128);   // (6, 64)
    linear_kernel<<<gl, 256>>>(hs, Wq, bq, 0);
    linear_kernel<<<gl, 256>>>(hs, Wk, bk, 1);
    linear_kernel<<<gl, 256>>>(hs, Wv, bv, 2);

    cudaFuncSetAttribute(attn_kernel, cudaFuncAttributeMaxDynamicSharedMemorySize, SMEM_ATTN);
    dim3 ga(Sc / 64, Hc, Bc);         // (32, 12, 4)
    attn_kernel<<<ga, 256, SMEM_ATTN>>>(lq, lk, mask, out);
}

// round 4
// speedup vs baseline: 3.9179x; 3.9179x over previous
#include <cuda_runtime.h>
#include <cstdint>

// ----------------------------------------------------------------------------
// Problem constants
// ----------------------------------------------------------------------------
#define Bc   4
#define Sc   2048
#define Dc   768
#define Hc   12
#define HDc  64
#define Mrows (Bc * Sc)   // 8192

// Scratch for projected q, k, v in [B, S, D] layout
__device__ float g_q[(size_t)Mrows * Dc];
__device__ float g_k[(size_t)Mrows * Dc];
__device__ float g_v[(size_t)Mrows * Dc];

// ----------------------------------------------------------------------------
// Helpers
// ----------------------------------------------------------------------------
__device__ __forceinline__ uint32_t tf32r(float x) {
    uint32_t u;
    asm("cvt.rna.tf32.f32 %0, %1;" : "=r"(u) : "f"(x));
    return u;
}
__device__ __forceinline__ float ftf32(float x) { return __uint_as_float(tf32r(x)); }

// d += a @ b  (m16n8k8, tf32 inputs, f32 accum)
__device__ __forceinline__ void mma8(float* d, const uint32_t* a, const uint32_t* b) {
    asm volatile(
        "mma.sync.aligned.m16n8k8.row.col.f32.tf32.tf32.f32 "
        "{%0,%1,%2,%3}, {%4,%5,%6,%7}, {%8,%9}, {%0,%1,%2,%3};\n"
        : "+f"(d[0]), "+f"(d[1]), "+f"(d[2]), "+f"(d[3])
        : "r"(a[0]), "r"(a[1]), "r"(a[2]), "r"(a[3]), "r"(b[0]), "r"(b[1]));
}

// ----------------------------------------------------------------------------
// Linear: Y = X @ W^T + b  [8192,768]x[768,768]
// 128x128x32 tiles, 8 warps (4x2), warp tile 32x64.
// ----------------------------------------------------------------------------
#define LPAD 36

__global__ __launch_bounds__(256) void linear_tc(
    const float* __restrict__ X,
    const float* __restrict__ Wq, const float* __restrict__ bq,
    const float* __restrict__ Wk, const float* __restrict__ bk,
    const float* __restrict__ Wv, const float* __restrict__ bv)
{
    __shared__ __align__(16) float As[128 * LPAD];
    __shared__ __align__(16) float Bs[128 * LPAD];

    const int z = blockIdx.z;
    const float* W    = (z == 0) ? Wq : (z == 1) ? Wk : Wv;
    const float* bias = (z == 0) ? bq : (z == 1) ? bk : bv;
    float* Y          = (z == 0) ? g_q : (z == 1) ? g_k : g_v;

    const int tid = threadIdx.x;
    const int wid = tid >> 5, lane = tid & 31;
    const int g = lane >> 2, tig = lane & 3;
    const int warpm = wid >> 1, warpn = wid & 1;
    const int bm = blockIdx.y * 128, bn = blockIdx.x * 128;

    float acc[2][8][4];
#pragma unroll
    for (int mt = 0; mt < 2; mt++)
#pragma unroll
        for (int nt = 0; nt < 8; nt++)
#pragma unroll
            for (int c = 0; c < 4; c++) acc[mt][nt][c] = 0.0f;

    for (int k0 = 0; k0 < Dc; k0 += 32) {
#pragma unroll
        for (int t = 0; t < 4; t++) {
            int idx = tid + t * 256;          // 0..1023
            int r  = idx >> 3;                // 0..127
            int c4 = (idx & 7) << 2;          // 0..28
            float4 va = *(const float4*)&X[(bm + r) * Dc + k0 + c4];
            float4 vb = *(const float4*)&W[(bn + r) * Dc + k0 + c4];
            va.x = ftf32(va.x); va.y = ftf32(va.y); va.z = ftf32(va.z); va.w = ftf32(va.w);
            vb.x = ftf32(vb.x); vb.y = ftf32(vb.y); vb.z = ftf32(vb.z); vb.w = ftf32(vb.w);
            *(float4*)&As[r * LPAD + c4] = va;
            *(float4*)&Bs[r * LPAD + c4] = vb;
        }
        __syncthreads();

#pragma unroll
        for (int kc = 0; kc < 4; kc++) {
            const int kk = kc * 8;
            uint32_t a[2][4], bfr[8][2];
#pragma unroll
            for (int mt = 0; mt < 2; mt++) {
                int row = warpm * 32 + mt * 16;
                a[mt][0] = __float_as_uint(As[(row + g)     * LPAD + kk + tig]);
                a[mt][1] = __float_as_uint(As[(row + g + 8) * LPAD + kk + tig]);
                a[mt][2] = __float_as_uint(As[(row + g)     * LPAD + kk + tig + 4]);
                a[mt][3] = __float_as_uint(As[(row + g + 8) * LPAD + kk + tig + 4]);
            }
#pragma unroll
            for (int nt = 0; nt < 8; nt++) {
                int col = warpn * 64 + nt * 8;
                bfr[nt][0] = __float_as_uint(Bs[(col + g) * LPAD + kk + tig]);
                bfr[nt][1] = __float_as_uint(Bs[(col + g) * LPAD + kk + tig + 4]);
            }
#pragma unroll
            for (int mt = 0; mt < 2; mt++)
#pragma unroll
                for (int nt = 0; nt < 8; nt++)
                    mma8(acc[mt][nt], a[mt], bfr[nt]);
        }
        __syncthreads();
    }

    // Epilogue: bias + store
#pragma unroll
    for (int mt = 0; mt < 2; mt++) {
        const int row0 = bm + warpm * 32 + mt * 16 + g;
#pragma unroll
        for (int nt = 0; nt < 8; nt++) {
            const int col = bn + warpn * 64 + nt * 8 + 2 * tig;
            const float bx = bias[col], by = bias[col + 1];
            *(float2*)&Y[row0 * Dc + col] =
                make_float2(acc[mt][nt][0] + bx, acc[mt][nt][1] + by);
            *(float2*)&Y[(row0 + 8) * Dc + col] =
                make_float2(acc[mt][nt][2] + bx, acc[mt][nt][3] + by);
        }
    }
}

// ----------------------------------------------------------------------------
// Flash attention, tf32 mma.sync.
// CTA = (b, h, 128-query tile). 256 threads (8 warps, 4x2).
// smem (floats): QS[128x132] augQ, KS[128x132] augK (reused as P),
//                VT[64x132] V^T, MS[128] mask, RMX[2][128], RSM[2][128].
// ----------------------------------------------------------------------------
#define APAD 132
#define OF_QS  0
#define OF_KS  16896
#define OF_VT  33792
#define OF_MS  42240
#define OF_RMX 42368
#define OF_RSM 42624
#define ATT_SMEM_F 42880
#define ATT_SMEM (ATT_SMEM_F * (int)sizeof(float))   // 171520

__global__ __launch_bounds__(256) void attn_tc(
    const float* __restrict__ lq_in,
    const float* __restrict__ lk_in,
    const float* __restrict__ mask,
    float* __restrict__ out)
{
    extern __shared__ __align__(16) float sm[];

    const int tid = threadIdx.x;
    const int wid = tid >> 5, lane = tid & 31;
    const int g = lane >> 2, tig = lane & 3;
    const int warpm = wid >> 1, warpn = wid & 1;

    const int b = blockIdx.z, h = blockIdx.y, q0 = blockIdx.x * 128;

    // ---- Load augmented Q = [q | lq] (128 rows x 128 dims), tf32-rounded
#pragma unroll
    for (int t = 0; t < 16; t++) {
        int idx = tid + t * 256;             // 0..4095
        int row = idx >> 5;                  // 0..127
        int c4  = (idx & 31) << 2;           // 0..124
        const float* src = (c4 < 64)
            ? (g_q  + (size_t)(b * Sc + q0 + row) * Dc + h * HDc + c4)
            : (lq_in + (size_t)(b * Sc + q0 + row) * Dc + h * HDc + (c4 - 64));
        float4 v = *(const float4*)src;
        v.x = ftf32(v.x); v.y = ftf32(v.y); v.z = ftf32(v.z); v.w = ftf32(v.w);
        *(float4*)&sm[OF_QS + row * APAD + c4] = v;
    }

    float m_run[4], l_run[4];
#pragma unroll
    for (int i = 0; i < 4; i++) { m_run[i] = -1e30f; l_run[i] = 0.0f; }
    float oacc[2][4][4];
#pragma unroll
    for (int mt = 0; mt < 2; mt++)
#pragma unroll
        for (int nt = 0; nt < 4; nt++)
#pragma unroll
            for (int c = 0; c < 4; c++) oacc[mt][nt][c] = 0.0f;

    // precompute this thread's 4 row indices (within 128-q tile)
    int rowi[4];
#pragma unroll
    for (int i = 0; i < 4; i++) rowi[i] = warpm * 32 + (i >> 1) * 16 + (i & 1) * 8 + g;

    for (int t = 0; t < Sc / 128; t++) {
        const int k0g = t * 128;
        const float* gk  = g_k   + (size_t)(b * Sc + k0g) * Dc + h * HDc;
        const float* glk = lk_in + (size_t)(b * Sc + k0g) * Dc + h * HDc;
        const float* gv  = g_v   + (size_t)(b * Sc + k0g) * Dc + h * HDc;

        __syncthreads();   // previous iteration fully done with KS/VT/MS

        // augK: [128 keys x 128 dims]
#pragma unroll
        for (int it = 0; it < 16; it++) {
            int idx = tid + it * 256;
            int key = idx >> 5;
            int c4  = (idx & 31) << 2;
            const float* src = (c4 < 64) ? (gk + key * Dc + c4) : (glk + key * Dc + (c4 - 64));
            float4 v = *(const float4*)src;
            v.x = ftf32(v.x); v.y = ftf32(v.y); v.z = ftf32(v.z); v.w = ftf32(v.w);
            *(float4*)&sm[OF_KS + key * APAD + c4] = v;
        }
        // V^T: [64 hd x 128 keys] (coalesced gmem column reads)
#pragma unroll
        for (int it = 0; it < 8; it++) {
            int idx = tid + it * 256;           // 0..2047
            int hd = idx & 63;
            int kb = (idx >> 6) << 2;           // 0,4,...,124
#pragma unroll
            for (int e = 0; e < 4; e++)
                sm[OF_VT + hd * APAD + kb + e] = ftf32(gv[(kb + e) * Dc + hd]);
        }
        if (tid < 128) sm[OF_MS + tid] = mask[b * Sc + k0g + tid];
        __syncthreads();

        // ---- Scores: S = augQ @ augK^T  (warp tile 32 rows x 64 keys)
        float sacc[2][8][4];
#pragma unroll
        for (int mt = 0; mt < 2; mt++)
#pragma unroll
            for (int nt = 0; nt < 8; nt++)
#pragma unroll
                for (int c = 0; c < 4; c++) sacc[mt][nt][c] = 0.0f;

#pragma unroll
        for (int kc = 0; kc < 16; kc++) {
            const int kk = kc * 8;
            uint32_t a[2][4], bfr[8][2];
#pragma unroll
            for (int mt = 0; mt < 2; mt++) {
                int row = warpm * 32 + mt * 16;
                a[mt][0] = __float_as_uint(sm[OF_QS + (row + g)     * APAD + kk + tig]);
                a[mt][1] = __float_as_uint(sm[OF_QS + (row + g + 8) * APAD + kk + tig]);
                a[mt][2] = __float_as_uint(sm[OF_QS + (row + g)     * APAD + kk + tig + 4]);
                a[mt][3] = __float_as_uint(sm[OF_QS + (row + g + 8) * APAD + kk + tig + 4]);
            }
#pragma unroll
            for (int nt = 0; nt < 8; nt++) {
                int col = warpn * 64 + nt * 8;
                bfr[nt][0] = __float_as_uint(sm[OF_KS + (col + g) * APAD + kk + tig]);
                bfr[nt][1] = __float_as_uint(sm[OF_KS + (col + g) * APAD + kk + tig + 4]);
            }
#pragma unroll
            for (int mt = 0; mt < 2; mt++)
#pragma unroll
                for (int nt = 0; nt < 8; nt++)
                    mma8(sacc[mt][nt], a[mt], bfr[nt]);
        }

        // ---- scale + mask + row max
        float rmax[4];
#pragma unroll
        for (int i = 0; i < 4; i++) rmax[i] = -1e30f;
#pragma unroll
        for (int mt = 0; mt < 2; mt++)
#pragma unroll
            for (int nt = 0; nt < 8; nt++) {
                int col = warpn * 64 + nt * 8 + 2 * tig;
                float m0 = sm[OF_MS + col], m1 = sm[OF_MS + col + 1];
                sacc[mt][nt][0] = sacc[mt][nt][0] * 0.125f + m0;
                sacc[mt][nt][1] = sacc[mt][nt][1] * 0.125f + m1;
                sacc[mt][nt][2] = sacc[mt][nt][2] * 0.125f + m0;
                sacc[mt][nt][3] = sacc[mt][nt][3] * 0.125f + m1;
                int i0 = mt * 2;
                rmax[i0]     = fmaxf(rmax[i0],     fmaxf(sacc[mt][nt][0], sacc[mt][nt][1]));
                rmax[i0 + 1] = fmaxf(rmax[i0 + 1], fmaxf(sacc[mt][nt][2], sacc[mt][nt][3]));
            }
#pragma unroll
        for (int i = 0; i < 4; i++) {
#pragma unroll
            for (int o = 1; o < 4; o <<= 1)
                rmax[i] = fmaxf(rmax[i], __shfl_xor_sync(0xffffffffu, rmax[i], o));
            sm[OF_RMX + warpn * 128 + rowi[i]] = rmax[i];
        }
        __syncthreads();   // also guarantees all score MMAs done before P overwrites KS

        float alpha[4], psum[4];
#pragma unroll
        for (int i = 0; i < 4; i++) {
            float mnew = fmaxf(m_run[i],
                               fmaxf(sm[OF_RMX + rowi[i]], sm[OF_RMX + 128 + rowi[i]]));
            alpha[i] = __expf(m_run[i] - mnew);
            m_run[i] = mnew;
            psum[i] = 0.0f;
        }

        // ---- P = exp(S - m), written into KS region (tf32-rounded)
#pragma unroll
        for (int mt = 0; mt < 2; mt++) {
            const int i0 = mt * 2;
            const int row = warpm * 32 + mt * 16 + g;
#pragma unroll
            for (int nt = 0; nt < 8; nt++) {
                const int col = warpn * 64 + nt * 8 + 2 * tig;
                float p0 = __expf(sacc[mt][nt][0] - m_run[i0]);
                float p1 = __expf(sacc[mt][nt][1] - m_run[i0]);
                float p2 = __expf(sacc[mt][nt][2] - m_run[i0 + 1]);
                float p3 = __expf(sacc[mt][nt][3] - m_run[i0 + 1]);
                psum[i0]     += p0 + p1;
                psum[i0 + 1] += p2 + p3;
                *(float2*)&sm[OF_KS + row * APAD + col]       = make_float2(ftf32(p0), ftf32(p1));
                *(float2*)&sm[OF_KS + (row + 8) * APAD + col] = make_float2(ftf32(p2), ftf32(p3));
            }
        }
#pragma unroll
        for (int i = 0; i < 4; i++) {
#pragma unroll
            for (int o = 1; o < 4; o <<= 1)
                psum[i] += __shfl_xor_sync(0xffffffffu, psum[i], o);
            sm[OF_RSM + warpn * 128 + rowi[i]] = psum[i];
        }
        __syncthreads();   // all P written + sums visible

#pragma unroll
        for (int i = 0; i < 4; i++)
            l_run[i] = l_run[i] * alpha[i] + sm[OF_RSM + rowi[i]] + sm[OF_RSM + 128 + rowi[i]];

        // rescale O accum
#pragma unroll
        for (int mt = 0; mt < 2; mt++)
#pragma unroll
            for (int nt = 0; nt < 4; nt++) {
                oacc[mt][nt][0] *= alpha[mt * 2];
                oacc[mt][nt][1] *= alpha[mt * 2];
                oacc[mt][nt][2] *= alpha[mt * 2 + 1];
                oacc[mt][nt][3] *= alpha[mt * 2 + 1];
            }

        // ---- O += P @ V^T^T  (warp tile 32 rows x 32 hd)
#pragma unroll
        for (int kc = 0; kc < 16; kc++) {
            const int kk = kc * 8;
            uint32_t a[2][4], bfr[4][2];
#pragma unroll
            for (int mt = 0; mt < 2; mt++) {
                int row = warpm * 32 + mt * 16;
                a[mt][0] = __float_as_uint(sm[OF_KS + (row + g)     * APAD + kk + tig]);
                a[mt][1] = __float_as_uint(sm[OF_KS + (row + g + 8) * APAD + kk + tig]);
                a[mt][2] = __float_as_uint(sm[OF_KS + (row + g)     * APAD + kk + tig + 4]);
                a[mt][3] = __float_as_uint(sm[OF_KS + (row + g + 8) * APAD + kk + tig + 4]);
            }
#pragma unroll
            for (int nt = 0; nt < 4; nt++) {
                int col = warpn * 32 + nt * 8;   // hd col
                bfr[nt][0] = __float_as_uint(sm[OF_VT + (col + g) * APAD + kk + tig]);
                bfr[nt][1] = __float_as_uint(sm[OF_VT + (col + g) * APAD + kk + tig + 4]);
            }
#pragma unroll
            for (int mt = 0; mt < 2; mt++)
#pragma unroll
                for (int nt = 0; nt < 4; nt++)
                    mma8(oacc[mt][nt], a[mt], bfr[nt]);
        }
    }

    // ---- Epilogue: out[b, q0+row, h*64+col] = O / l
    float inv[4];
#pragma unroll
    for (int i = 0; i < 4; i++) inv[i] = 1.0f / l_run[i];
#pragma unroll
    for (int mt = 0; mt < 2; mt++) {
        const int r0 = q0 + warpm * 32 + mt * 16 + g;
#pragma unroll
        for (int nt = 0; nt < 4; nt++) {
            const int col = h * HDc + warpn * 32 + nt * 8 + 2 * tig;
            *(float2*)&out[(size_t)(b * Sc + r0) * Dc + col] =
                make_float2(oacc[mt][nt][0] * inv[mt * 2], oacc[mt][nt][1] * inv[mt * 2]);
            *(float2*)&out[(size_t)(b * Sc + r0 + 8) * Dc + col] =
                make_float2(oacc[mt][nt][2] * inv[mt * 2 + 1], oacc[mt][nt][3] * inv[mt * 2 + 1]);
        }
    }
}

// ----------------------------------------------------------------------------
// Launch
// ----------------------------------------------------------------------------
extern "C" void kernel_launch(void* const* d_in, const int* in_sizes, int n_in,
                              void* d_out, int out_size)
{
    const float* hs   = (const float*)d_in[0];
    const float* lq   = (const float*)d_in[1];
    const float* lk   = (const float*)d_in[2];
    const float* mask = (const float*)d_in[3];
    const float* Wq   = (const float*)d_in[4];
    const float* bq   = (const float*)d_in[5];
    const float* Wk   = (const float*)d_in[6];
    const float* bk   = (const float*)d_in[7];
    const float* Wv   = (const float*)d_in[8];
    const float* bv   = (const float*)d_in[9];
    float* out = (float*)d_out;

    dim3 gl(Dc / 128, Mrows / 128, 3);   // (6, 64, 3)
    linear_tc<<<gl, 256>>>(hs, Wq, bq, Wk, bk, Wv, bv);

    cudaFuncSetAttribute(attn_tc, cudaFuncAttributeMaxDynamicSharedMemorySize, ATT_SMEM);
    dim3 ga(Sc / 128, Hc, Bc);           // (16, 12, 4)
    attn_tc<<<ga, 256, ATT_SMEM>>>(lq, lk, mask, out);
}